// round 15
// baseline (speedup 1.0000x reference)
#include <cuda_runtime.h>
#include <math.h>

#define H 8
#define NNODES 4096
#define D 64
#define BLOCK_THREADS 128
#define F4_PER_THREAD 2
#define ROWS_PER_BLOCK 16   // 128 thr * 2 f4 * 4 floats / 64 = 16 rows
#define NBLOCKS (H * NNODES / ROWS_PER_BLOCK)  // 2048
#define GROUPS 2            // general path: 2 row-groups of 64 threads

// out[h,n,:] = beta_h*(P@v)[n,:] + (alpha_h - beta_h*P[n,n]) * v[h,n,:]
// with P = softmax(q·K^T/8 + adj). When beta_h == 0 this is exactly
// out = alpha_h * v (softmax finite, 0*finite == 0 in fp32): scaled-copy
// path. R6..R14 sweep shows all sane shapes sit on a ~6.6us launch floor;
// this round tests the last untried corner (2048x128, MLP=2) with per-slot
// store interleaving so the first STG drains while later LDGs are in flight.
__global__ __launch_bounds__(BLOCK_THREADS) void attn_adj_kernel(
        const float* __restrict__ q,
        const float* __restrict__ k,
        const float* __restrict__ v,
        const float* __restrict__ adj,
        const float* __restrict__ alpha,
        const float* __restrict__ beta,
        float* __restrict__ out) {
    const int t = threadIdx.x;
    // 1D grid over flattened rows; head = row >> 12. 32-bit indices
    // throughout (max float index 2,097,152 << 2^31).
    const int row0 = blockIdx.x * ROWS_PER_BLOCK;
    const int h = row0 >> 12;
    const int blk_base4 = row0 * (D / 4);

    // front-batch both LDG.128 (independent), params in parallel
    const float4* __restrict__ src = (const float4*)v + blk_base4;
    float4 r0 = src[t];
    float4 r1 = src[t + BLOCK_THREADS];
    const float b = beta[h];
    const float a = alpha[h];

    if (b == 0.0f) {
        float4* __restrict__ dst = (float4*)out + blk_base4;
        // per-slot interleave: first store issues while nothing else pends
        r0.x *= a; r0.y *= a; r0.z *= a; r0.w *= a;
        dst[t] = r0;
        r1.x *= a; r1.y *= a; r1.z *= a; r1.w *= a;
        dst[t + BLOCK_THREADS] = r1;
        return;
    }

    // ---- general path: 2 rows in parallel (64 threads each), 8 passes ----
    const int g = t >> 6;   // row-group 0..1
    const int d = t & 63;   // dimension 0..63

    __shared__ float qs[GROUPS][D];
    __shared__ float ebuf[GROUPS][64];
    __shared__ float red[GROUPS][64];
    __shared__ float pe_sh[GROUPS];

    const float* kh = k + h * NNODES * D;
    const float* vh = v + h * NNODES * D;
    const int n0 = row0 & (NNODES - 1);

    for (int it = 0; it < ROWS_PER_BLOCK / GROUPS; it++) {
        const int n = n0 + it * GROUPS + g;
        const int base = (h * NNODES + n) * D;
        const float* adjrow = adj + ((long long)h * NNODES + n) * NNODES;

        qs[g][d] = q[base + d];
        if (d == 0) pe_sh[g] = 0.0f;
        __syncthreads();

        float m_run = -INFINITY;
        float l_run = 0.0f;
        float acc = 0.0f;   // this thread's dimension-d accumulator
        float pnn = 0.0f;   // unnormalized e at the diagonal

        for (int m0 = 0; m0 < NNODES; m0 += 64) {
            const int m = m0 + d;
            const float* kr = kh + m * D;
            float s = 0.0f;
            #pragma unroll
            for (int j = 0; j < D; j++) s += qs[g][j] * kr[j];
            s = s * 0.125f + adjrow[m];

            // chunk max (64-wide reduction within the group)
            red[g][d] = s;
            __syncthreads();
            #pragma unroll
            for (int off = 32; off > 0; off >>= 1) {
                if (d < off) red[g][d] = fmaxf(red[g][d], red[g][d + off]);
                __syncthreads();
            }
            const float m_new = fmaxf(m_run, red[g][0]);
            const float corr = expf(m_run - m_new);  // expf(-inf)=0 first iter
            const float ev = expf(s - m_new);
            __syncthreads();  // everyone done reading red[g][0]

            ebuf[g][d] = ev;
            red[g][d] = ev;
            if (m == n) pe_sh[g] = ev;   // at most once over the whole loop
            __syncthreads();
            #pragma unroll
            for (int off = 32; off > 0; off >>= 1) {
                if (d < off) red[g][d] += red[g][d + off];
                __syncthreads();
            }
            l_run = l_run * corr + red[g][0];

            const float pchunk = (m0 <= n && n < m0 + 64) ? pe_sh[g] : 0.0f;
            pnn = pnn * corr + pchunk;

            acc *= corr;
            #pragma unroll 8
            for (int j = 0; j < 64; j++)
                acc += ebuf[g][j] * vh[(m0 + j) * D + d];
            __syncthreads();  // done reading ebuf/red/pe_sh before next write
            if (d == 0) pe_sh[g] = 0.0f;
        }

        const float inv_l = 1.0f / l_run;
        out[base + d] = b * acc * inv_l + (a - b * pnn * inv_l) * v[base + d];
        __syncthreads();  // before qs[g] is overwritten next row-pass
    }
}

extern "C" void kernel_launch(void* const* d_in, const int* in_sizes, int n_in,
                              void* d_out, int out_size) {
    const float* q     = (const float*)d_in[0];
    const float* k     = (const float*)d_in[1];
    const float* v     = (const float*)d_in[2];
    const float* adj   = (const float*)d_in[3];
    const float* alpha = (const float*)d_in[4];
    const float* beta  = (const float*)d_in[5];
    float* out = (float*)d_out;

    attn_adj_kernel<<<NBLOCKS, BLOCK_THREADS>>>(  // 2048 x 128
        q, k, v, adj, alpha, beta, out);
}